// round 12
// baseline (speedup 1.0000x reference)
#include <cuda_runtime.h>
#include <cuda_bf16.h>
#include <cstdint>

// Problem constants
#define NN 10000
#define EE 128000
#define CC 128
#define AA 10
#define FF 8
#define MSGW 1152
#define OUTR_ELEMS (NN * CC * 9)

// ---------------- scratch (device globals) ---------------------------------
__device__ float g_h[NN * CC];
__device__ float g_tpw[(long)EE * 384];   // NOW INDEXED BY CSR SLOT, not edge
__device__ float g_msg_r[NN * MSGW];
__device__ float g_msg_i[NN * MSGW];
__device__ int   g_deg[NN];
__device__ int   g_cur[NN];
__device__ int   g_off[NN + 1];
__device__ int   g_elist[EE];
__device__ int   g_slist[EE];
__device__ int   g_slot[EE];              // e -> slot map
__device__ float g_t3t[64 * EE];          // T3 transposed [u][e]

__device__ __forceinline__ float silu(float x) {
    return x * (1.0f / (1.0f + __expf(-x)));
}

// f32x2 packed helpers
__device__ __forceinline__ unsigned long long pack2(float lo, float hi) {
    unsigned long long r;
    asm("mov.b64 %0, {%1, %2};" : "=l"(r) : "f"(lo), "f"(hi));
    return r;
}
__device__ __forceinline__ void unpack2(unsigned long long v, float& lo, float& hi) {
    asm("mov.b64 {%0, %1}, %2;" : "=f"(lo), "=f"(hi) : "l"(v));
}
__device__ __forceinline__ void ffma2(unsigned long long& acc,
                                      unsigned long long a, unsigned long long b) {
    asm("fma.rn.f32x2 %0, %1, %2, %0;" : "+l"(acc) : "l"(a), "l"(b));
}

// ---------------- CSR build -------------------------------------------------
__global__ void k_reset() {
    int t = blockIdx.x * 256 + threadIdx.x;
    if (t < NN) { g_deg[t] = 0; g_cur[t] = 0; }
}
__global__ void k_count(const int* __restrict__ eidx) {
    int e = blockIdx.x * 256 + threadIdx.x;
    if (e < EE) atomicAdd(&g_deg[eidx[EE + e]], 1);
}
__global__ void k_scan() {
    __shared__ int part[1024];
    int t = threadIdx.x;
    int base = t * 10;
    int s = 0;
    if (t < 1000)
        for (int i = 0; i < 10; i++) s += g_deg[base + i];
    part[t] = s;
    __syncthreads();
    for (int d = 1; d < 1024; d <<= 1) {
        int v = (t >= d) ? part[t - d] : 0;
        __syncthreads();
        part[t] += v;
        __syncthreads();
    }
    int excl = (t == 0) ? 0 : part[t - 1];
    if (t < 1000) {
        int run = excl;
        for (int i = 0; i < 10; i++) { g_off[base + i] = run; run += g_deg[base + i]; }
        if (t == 999) g_off[NN] = run;
    }
}
__global__ void k_fill(const int* __restrict__ eidx) {
    int e = blockIdx.x * 256 + threadIdx.x;
    if (e < EE) {
        int r = eidx[EE + e];
        int s = eidx[e];
        int pos = atomicAdd(&g_cur[r], 1);
        int slot = g_off[r] + pos;
        g_elist[slot] = e;
        g_slist[slot] = s;
        g_slot[e] = slot;
    }
}

// ---------------- h = node_feats @ W_up ------------------------------------
#define H_SMEM ((128 * 128 + 32 * 128) * 4)
__global__ __launch_bounds__(256) void k_h(const float* __restrict__ feats,
                                           const float* __restrict__ Wup) {
    extern __shared__ float sm[];
    float* sW = sm;
    float* sF = sm + 16384;
    int n0 = blockIdx.x * 32;
    int t = threadIdx.x;
    for (int i = t; i < 16384; i += 256) sW[i] = Wup[i];
    for (int i = t; i < 4096; i += 256) {
        int n = n0 + (i >> 7);
        sF[i] = (n < NN) ? feats[n * CC + (i & 127)] : 0.f;
    }
    __syncthreads();
    int tk = (t & 31) * 4;
    int tn = (t >> 5) * 4;
    float acc[4][4] = {};
    for (int u = 0; u < 128; u++) {
        float4 b = *(const float4*)&sW[u * 128 + tk];
        #pragma unroll
        for (int i = 0; i < 4; i++) {
            float a = sF[(tn + i) * 128 + u];
            acc[i][0] = fmaf(a, b.x, acc[i][0]);
            acc[i][1] = fmaf(a, b.y, acc[i][1]);
            acc[i][2] = fmaf(a, b.z, acc[i][2]);
            acc[i][3] = fmaf(a, b.w, acc[i][3]);
        }
    }
    #pragma unroll
    for (int i = 0; i < 4; i++) {
        int n = n0 + tn + i;
        if (n < NN) {
            float4 v = make_float4(acc[i][0], acc[i][1], acc[i][2], acc[i][3]);
            *(float4*)&g_h[n * CC + tk] = v;
        }
    }
}

// ---------------- sc: 64 nodes x 512 threads (f32x2) ------------------------
#define SC_SMEM ((64 * 128 + 640 + 64 * 80 + 80 * 128) * 4)
__global__ __launch_bounds__(512) void k_sc(const float* __restrict__ feats,
                                            const float* __restrict__ attrs,
                                            const float* __restrict__ Wskip,
                                            float* __restrict__ sc_out) {
    extern __shared__ float sm[];
    float* sF = sm;
    float* sA = sF + 8192;
    float* sX = sA + 640;
    float* sW = sX + 5120;
    int n0 = blockIdx.x * 64;
    int t = threadIdx.x;
    for (int i = t; i < 8192; i += 512) {
        int n = n0 + (i >> 7);
        sF[i] = (n < NN) ? feats[n * CC + (i & 127)] : 0.f;
    }
    for (int i = t; i < 640; i += 512) {
        int n = n0 + i / 10;
        sA[i] = (n < NN) ? attrs[n * AA + i % 10] : 0.f;
    }
    int tk = (t & 31) * 4;
    int tn = (t >> 5) * 4;
    unsigned long long acc[4][2] = {};
    for (int uc = 0; uc < 16; uc++) {
        __syncthreads();
        for (int i = t; i < 10240; i += 512) sW[i] = Wskip[uc * 10240 + i];
        for (int idx = t; idx < 5120; idx += 512) {
            int n = idx / 80, i = idx % 80;
            sX[idx] = sF[n * 128 + uc * 8 + i / 10] * sA[n * 10 + i % 10];
        }
        __syncthreads();
        for (int i = 0; i < 80; i++) {
            ulonglong2 w = *(const ulonglong2*)&sW[i * 128 + tk];
            #pragma unroll
            for (int ii = 0; ii < 4; ii++) {
                float a = sX[(tn + ii) * 80 + i];
                unsigned long long A = pack2(a, a);
                ffma2(acc[ii][0], A, w.x);
                ffma2(acc[ii][1], A, w.y);
            }
        }
    }
    #pragma unroll
    for (int ii = 0; ii < 4; ii++) {
        int n = n0 + tn + ii;
        if (n < NN) {
            float f0, f1, f2, f3;
            unpack2(acc[ii][0], f0, f1);
            unpack2(acc[ii][1], f2, f3);
            *(float4*)&sc_out[n * CC + tk] = make_float4(f0, f1, f2, f3);
        }
    }
}

// ---------------- MLP layers 1-3 -------------------------------------------
#define MLP_SMEM ((512 + 4096 + 4096 + 512 + 4096 + 4096) * 4)
__global__ __launch_bounds__(256) void k_mlp123(const float* __restrict__ ef,
                                                const float* __restrict__ W1,
                                                const float* __restrict__ W2,
                                                const float* __restrict__ W3) {
    extern __shared__ float sm[];
    float* sW1 = sm;               // 512
    float* sW2 = sW1 + 512;        // 4096
    float* sW3 = sW2 + 4096;       // 4096
    float* sEF = sW3 + 4096;       // 512
    float* sTA = sEF + 512;        // 4096
    float* sTB = sTA + 4096;       // 4096
    float* sT3 = sEF;              // reuse (64*65=4160 <= 4608)
    int t = threadIdx.x;
    for (int i = t; i < 512; i += 256) sW1[i] = W1[i];
    for (int i = t; i < 4096; i += 256) sW2[i] = W2[i];
    for (int i = t; i < 4096; i += 256) sW3[i] = W3[i];
    int e0 = blockIdx.x * 64;
    for (int i = t; i < 512; i += 256) sEF[i] = ef[e0 * FF + i];
    __syncthreads();
    for (int o = t; o < 4096; o += 256) {
        int e = o >> 6, j = o & 63;
        float acc = 0.f;
        #pragma unroll
        for (int f = 0; f < 8; f++) acc = fmaf(sEF[e * 8 + f], sW1[f * 64 + j], acc);
        sTA[o] = silu(acc);
    }
    __syncthreads();
    int j0 = (t & 15) * 4, el = (t >> 4) * 4;
    {
        float acc[4][4] = {};
        for (int u = 0; u < 64; u++) {
            float4 b = *(const float4*)&sW2[u * 64 + j0];
            #pragma unroll
            for (int i = 0; i < 4; i++) {
                float a = sTA[(el + i) * 64 + u];
                acc[i][0] = fmaf(a, b.x, acc[i][0]);
                acc[i][1] = fmaf(a, b.y, acc[i][1]);
                acc[i][2] = fmaf(a, b.z, acc[i][2]);
                acc[i][3] = fmaf(a, b.w, acc[i][3]);
            }
        }
        #pragma unroll
        for (int i = 0; i < 4; i++)
            #pragma unroll
            for (int j = 0; j < 4; j++) sTB[(el + i) * 64 + j0 + j] = silu(acc[i][j]);
    }
    __syncthreads();
    {
        float acc[4][4] = {};
        for (int u = 0; u < 64; u++) {
            float4 b = *(const float4*)&sW3[u * 64 + j0];
            #pragma unroll
            for (int i = 0; i < 4; i++) {
                float a = sTB[(el + i) * 64 + u];
                acc[i][0] = fmaf(a, b.x, acc[i][0]);
                acc[i][1] = fmaf(a, b.y, acc[i][1]);
                acc[i][2] = fmaf(a, b.z, acc[i][2]);
                acc[i][3] = fmaf(a, b.w, acc[i][3]);
            }
        }
        #pragma unroll
        for (int i = 0; i < 4; i++)
            #pragma unroll
            for (int j = 0; j < 4; j++)
                sT3[(j0 + j) * 65 + el + i] = silu(acc[i][j]);
    }
    __syncthreads();
    for (int i = t; i < 4096; i += 256) {
        int u = i >> 6, e = i & 63;
        g_t3t[u * EE + e0 + e] = sT3[u * 65 + e];
    }
}

// ---------------- layer 4 GEMM: tpw[slot[e]] = T3[e] @ W4 ------------------
// Output rows scattered to CSR-slot order so k_gather reads sequentially.
#define G4_SMEM ((8192 + 8192) * 4)
__global__ __launch_bounds__(256) void k_gemm4(const float* __restrict__ W4) {
    extern __shared__ float sm[];
    float* sW = sm;            // 64 x 128 (this pass's j slice)
    float* sA = sm + 8192;     // 64 x 128
    int t = threadIdx.x;
    int e0 = blockIdx.x * 128;
    int jp = blockIdx.y * 128;
    for (int i = t; i < 8192; i += 256) {
        int u = i >> 7, j = i & 127;
        sW[i] = W4[u * 384 + jp + j];
    }
    for (int i = t; i < 2048; i += 256) {
        int u = i >> 5, e4 = (i & 31) * 4;
        *(float4*)&sA[u * 128 + e4] = *(const float4*)&g_t3t[u * EE + e0 + e4];
    }
    __syncthreads();
    int jg = t & 15, eg = t >> 4;
    int el = eg * 8, jb = jg * 8;
    unsigned long long acc[8][4] = {};
    #pragma unroll 4
    for (int u = 0; u < 64; u++) {
        float4 a03 = *(const float4*)&sA[u * 128 + el];
        float4 a47 = *(const float4*)&sA[u * 128 + el + 4];
        ulonglong2 wA = *(const ulonglong2*)&sW[u * 128 + jb];
        ulonglong2 wB = *(const ulonglong2*)&sW[u * 128 + jb + 4];
        unsigned long long A0 = pack2(a03.x, a03.x);
        unsigned long long A1 = pack2(a03.y, a03.y);
        unsigned long long A2 = pack2(a03.z, a03.z);
        unsigned long long A3 = pack2(a03.w, a03.w);
        unsigned long long A4 = pack2(a47.x, a47.x);
        unsigned long long A5 = pack2(a47.y, a47.y);
        unsigned long long A6 = pack2(a47.z, a47.z);
        unsigned long long A7 = pack2(a47.w, a47.w);
        ffma2(acc[0][0], A0, wA.x); ffma2(acc[0][1], A0, wA.y);
        ffma2(acc[0][2], A0, wB.x); ffma2(acc[0][3], A0, wB.y);
        ffma2(acc[1][0], A1, wA.x); ffma2(acc[1][1], A1, wA.y);
        ffma2(acc[1][2], A1, wB.x); ffma2(acc[1][3], A1, wB.y);
        ffma2(acc[2][0], A2, wA.x); ffma2(acc[2][1], A2, wA.y);
        ffma2(acc[2][2], A2, wB.x); ffma2(acc[2][3], A2, wB.y);
        ffma2(acc[3][0], A3, wA.x); ffma2(acc[3][1], A3, wA.y);
        ffma2(acc[3][2], A3, wB.x); ffma2(acc[3][3], A3, wB.y);
        ffma2(acc[4][0], A4, wA.x); ffma2(acc[4][1], A4, wA.y);
        ffma2(acc[4][2], A4, wB.x); ffma2(acc[4][3], A4, wB.y);
        ffma2(acc[5][0], A5, wA.x); ffma2(acc[5][1], A5, wA.y);
        ffma2(acc[5][2], A5, wB.x); ffma2(acc[5][3], A5, wB.y);
        ffma2(acc[6][0], A6, wA.x); ffma2(acc[6][1], A6, wA.y);
        ffma2(acc[6][2], A6, wB.x); ffma2(acc[6][3], A6, wB.y);
        ffma2(acc[7][0], A7, wA.x); ffma2(acc[7][1], A7, wA.y);
        ffma2(acc[7][2], A7, wB.x); ffma2(acc[7][3], A7, wB.y);
    }
    #pragma unroll
    for (int i = 0; i < 8; i++) {
        float f0, f1, f2, f3, f4, f5, f6, f7;
        unpack2(acc[i][0], f0, f1);
        unpack2(acc[i][1], f2, f3);
        unpack2(acc[i][2], f4, f5);
        unpack2(acc[i][3], f6, f7);
        int slot = g_slot[e0 + el + i];
        long base = (long)slot * 384 + jp + jb;
        *(float4*)&g_tpw[base]     = make_float4(f0, f1, f2, f3);
        *(float4*)&g_tpw[base + 4] = make_float4(f4, f5, f6, f7);
    }
}

// ---------------- gather: R9 form, tpw read SEQUENTIALLY by slot ------------
// 1 warp per node, 4 channels/thread. 8 nodes / 256-thread block.
__global__ __launch_bounds__(256) void k_gather(const float* __restrict__ yr,
                                                const float* __restrict__ yi) {
    int t = threadIdx.x;
    int n = blockIdx.x * 8 + (t >> 5);
    int c0 = (t & 31) * 4;
    float4 ar[9], ai[9];
    #pragma unroll
    for (int m = 0; m < 9; m++) {
        ar[m] = make_float4(0.f, 0.f, 0.f, 0.f);
        ai[m] = make_float4(0.f, 0.f, 0.f, 0.f);
    }
    int beg = g_off[n], end = g_off[n + 1];
    #pragma unroll 2
    for (int i = beg; i < end; i++) {
        int e = g_elist[i];
        int s = g_slist[i];
        float4 x  = *(const float4*)&g_h[s * CC + c0];
        const float* tw = g_tpw + (long)i * 384;   // slot order = loop index
        float4 t0 = *(const float4*)&tw[c0];
        float4 t1 = *(const float4*)&tw[128 + c0];
        float4 t2 = *(const float4*)&tw[256 + c0];
        float4 xw0 = make_float4(x.x * t0.x, x.y * t0.y, x.z * t0.z, x.w * t0.w);
        float4 xw1 = make_float4(x.x * t1.x, x.y * t1.y, x.z * t1.z, x.w * t1.w);
        float4 xw2 = make_float4(x.x * t2.x, x.y * t2.y, x.z * t2.z, x.w * t2.w);
        const float* yre = yr + e * 9;
        const float* yie = yi + e * 9;
        #pragma unroll
        for (int m = 0; m < 9; m++) {
            float4 xw = (m == 0) ? xw0 : (m < 4) ? xw1 : xw2;
            float vr = yre[m], vi = yie[m];
            ar[m].x = fmaf(xw.x, vr, ar[m].x); ar[m].y = fmaf(xw.y, vr, ar[m].y);
            ar[m].z = fmaf(xw.z, vr, ar[m].z); ar[m].w = fmaf(xw.w, vr, ar[m].w);
            ai[m].x = fmaf(xw.x, vi, ai[m].x); ai[m].y = fmaf(xw.y, vi, ai[m].y);
            ai[m].z = fmaf(xw.z, vi, ai[m].z); ai[m].w = fmaf(xw.w, vi, ai[m].w);
        }
    }
    float* mr = g_msg_r + n * MSGW;
    float* mi = g_msg_i + n * MSGW;
    *(float4*)&mr[c0] = ar[0];
    *(float4*)&mi[c0] = ai[0];
    #pragma unroll
    for (int m = 0; m < 3; m++) {
        *(float4*)&mr[128 + m * 128 + c0] = ar[1 + m];
        *(float4*)&mi[128 + m * 128 + c0] = ai[1 + m];
    }
    #pragma unroll
    for (int m = 0; m < 5; m++) {
        *(float4*)&mr[512 + m * 128 + c0] = ar[4 + m];
        *(float4*)&mi[512 + m * 128 + c0] = ai[4 + m];
    }
}

// ---------------- linear_irreps: in-place writeback into g_msg -------------
#define LIN_SMEM ((128 * 128 + 2 * 32 * 128) * 4)
__global__ __launch_bounds__(256) void k_linear(const float* __restrict__ W,
                                                int d, int loff) {
    extern __shared__ float sm[];
    float* sW  = sm;
    float* sAr = sm + 16384;
    float* sAi = sAr + 4096;
    int nrows = NN * d;
    int t = threadIdx.x;
    for (int i = t; i < 16384; i += 256) sW[i] = W[i];
    int tk = (t & 31) * 4;
    int tr = (t >> 5) * 4;
    for (int r0 = blockIdx.x * 32; r0 < nrows; r0 += gridDim.x * 32) {
        __syncthreads();
        for (int i = t; i < 4096; i += 256) {
            int rl = i >> 7, u = i & 127;
            int row = r0 + rl;
            float vr = 0.f, vi = 0.f;
            if (row < nrows) {
                int n = row / d, m = row % d;
                int off = n * MSGW + loff + m * 128 + u;
                vr = g_msg_r[off];
                vi = g_msg_i[off];
            }
            sAr[i] = vr;
            sAi[i] = vi;
        }
        __syncthreads();
        unsigned long long accr[4][2] = {};
        unsigned long long acci[4][2] = {};
        for (int u = 0; u < 128; u++) {
            ulonglong2 w = *(const ulonglong2*)&sW[u * 128 + tk];
            #pragma unroll
            for (int i = 0; i < 4; i++) {
                float a = sAr[(tr + i) * 128 + u];
                unsigned long long A = pack2(a, a);
                ffma2(accr[i][0], A, w.x);
                ffma2(accr[i][1], A, w.y);
                float c = sAi[(tr + i) * 128 + u];
                unsigned long long Cc = pack2(c, c);
                ffma2(acci[i][0], Cc, w.x);
                ffma2(acci[i][1], Cc, w.y);
            }
        }
        #pragma unroll
        for (int i = 0; i < 4; i++) {
            int row = r0 + tr + i;
            if (row < nrows) {
                int n = row / d, m = row % d;
                int off = n * MSGW + loff + m * 128 + tk;
                float r01[4], i01[4];
                unpack2(accr[i][0], r01[0], r01[1]);
                unpack2(accr[i][1], r01[2], r01[3]);
                unpack2(acci[i][0], i01[0], i01[1]);
                unpack2(acci[i][1], i01[2], i01[3]);
                *(float4*)&g_msg_r[off] = make_float4(r01[0], r01[1], r01[2], r01[3]);
                *(float4*)&g_msg_i[off] = make_float4(i01[0], i01[1], i01[2], i01[3]);
            }
        }
    }
}

// ---------------- transpose [mo*128+k] -> [k*9+mo] per node ----------------
__global__ __launch_bounds__(256) void k_transpose(float* __restrict__ out_r,
                                                   float* __restrict__ out_i) {
    __shared__ float sr[8 * MSGW];
    __shared__ float si[8 * MSGW];
    int t = threadIdx.x;
    int n0 = blockIdx.x * 8;
    for (int i = t; i < 2304; i += 256) {
        int nd = i / 288, o4 = (i % 288) * 4;
        *(float4*)&sr[nd * MSGW + o4] = *(const float4*)&g_msg_r[(n0 + nd) * MSGW + o4];
        *(float4*)&si[nd * MSGW + o4] = *(const float4*)&g_msg_i[(n0 + nd) * MSGW + o4];
    }
    __syncthreads();
    for (int i = t; i < 2304; i += 256) {
        int nd = i / 288, o4 = (i % 288) * 4;
        const float* br = sr + nd * MSGW;
        const float* bi = si + nd * MSGW;
        float vr[4], vi[4];
        #pragma unroll
        for (int c = 0; c < 4; c++) {
            int oidx = o4 + c;
            int k = oidx / 9;
            int mo = oidx - 9 * k;
            vr[c] = br[mo * 128 + k];
            vi[c] = bi[mo * 128 + k];
        }
        long ob = (long)(n0 + nd) * MSGW + o4;
        *(float4*)&out_r[ob] = make_float4(vr[0], vr[1], vr[2], vr[3]);
        *(float4*)&out_i[ob] = make_float4(vi[0], vi[1], vi[2], vi[3]);
    }
}

// ---------------- launch ---------------------------------------------------
extern "C" void kernel_launch(void* const* d_in, const int* in_sizes, int n_in,
                              void* d_out, int out_size) {
    const float* node_attrs = (const float*)d_in[0];
    const float* node_feats = (const float*)d_in[1];
    const float* yr        = (const float*)d_in[2];
    const float* yi        = (const float*)d_in[3];
    const float* ef        = (const float*)d_in[4];
    const int*   eidx      = (const int*)  d_in[5];
    const float* Wup       = (const float*)d_in[6];
    const float* Wskip     = (const float*)d_in[7];
    const float* W1        = (const float*)d_in[8];
    const float* W2        = (const float*)d_in[9];
    const float* W3        = (const float*)d_in[10];
    const float* W4        = (const float*)d_in[11];
    const float* Wl0       = (const float*)d_in[12];
    const float* Wl1       = (const float*)d_in[13];
    const float* Wl2       = (const float*)d_in[14];

    float* out   = (float*)d_out;
    float* out_r = out;
    float* out_i = out + OUTR_ELEMS;
    float* out_s = out + 2 * OUTR_ELEMS;

    cudaFuncSetAttribute(k_h,      cudaFuncAttributeMaxDynamicSharedMemorySize, H_SMEM);
    cudaFuncSetAttribute(k_sc,     cudaFuncAttributeMaxDynamicSharedMemorySize, SC_SMEM);
    cudaFuncSetAttribute(k_mlp123, cudaFuncAttributeMaxDynamicSharedMemorySize, MLP_SMEM);
    cudaFuncSetAttribute(k_gemm4,  cudaFuncAttributeMaxDynamicSharedMemorySize, G4_SMEM);
    cudaFuncSetAttribute(k_linear, cudaFuncAttributeMaxDynamicSharedMemorySize, LIN_SMEM);

    // idx 0..2
    k_mlp123<<<EE / 64, 256, MLP_SMEM>>>(ef, W1, W2, W3);
    k_reset<<<(NN + 255) / 256, 256>>>();
    k_count<<<(EE + 255) / 256, 256>>>(eidx);
    // idx 3: profiled launch (k_sc 512-thread variant — first measurement)
    k_sc<<<(NN + 63) / 64, 512, SC_SMEM>>>(node_feats, node_attrs, Wskip, out_s);
    // idx 4..7 (fill must precede gemm4: g_slot)
    k_scan<<<1, 1024>>>();
    k_fill<<<(EE + 255) / 256, 256>>>(eidx);
    k_gemm4<<<dim3(EE / 128, 3), 256, G4_SMEM>>>(W4);
    k_h<<<(NN + 31) / 32, 256, H_SMEM>>>(node_feats, Wup);
    // idx 8
    k_gather<<<NN / 8, 256>>>(yr, yi);
    // idx 9..11: linear (in-place writeback into g_msg)
    k_linear<<<296, 256, LIN_SMEM>>>(Wl0, 1, 0);
    k_linear<<<296, 256, LIN_SMEM>>>(Wl1, 3, 128);
    k_linear<<<296, 256, LIN_SMEM>>>(Wl2, 5, 512);
    // idx 12: layout transpose to out
    k_transpose<<<NN / 8, 256>>>(out_r, out_i);
}

// round 13
// speedup vs baseline: 1.0251x; 1.0251x over previous
#include <cuda_runtime.h>
#include <cuda_bf16.h>
#include <cstdint>

// Problem constants
#define NN 10000
#define EE 128000
#define CC 128
#define AA 10
#define FF 8
#define MSGW 1152
#define OUTR_ELEMS (NN * CC * 9)

// ---------------- scratch (device globals) ---------------------------------
__device__ float g_h[NN * CC];
__device__ float g_tpw[(long)EE * 384];
__device__ float g_msg_r[NN * MSGW];
__device__ float g_msg_i[NN * MSGW];
__device__ int   g_deg[NN];
__device__ int   g_cur[NN];
__device__ int   g_off[NN + 1];
__device__ int   g_elist[EE];
__device__ int   g_slist[EE];
__device__ float g_t3t[64 * EE];          // T3 transposed [u][e]

__device__ __forceinline__ float silu(float x) {
    return x * (1.0f / (1.0f + __expf(-x)));
}

// f32x2 packed helpers
__device__ __forceinline__ unsigned long long pack2(float lo, float hi) {
    unsigned long long r;
    asm("mov.b64 %0, {%1, %2};" : "=l"(r) : "f"(lo), "f"(hi));
    return r;
}
__device__ __forceinline__ void unpack2(unsigned long long v, float& lo, float& hi) {
    asm("mov.b64 {%0, %1}, %2;" : "=f"(lo), "=f"(hi) : "l"(v));
}
__device__ __forceinline__ void ffma2(unsigned long long& acc,
                                      unsigned long long a, unsigned long long b) {
    asm("fma.rn.f32x2 %0, %1, %2, %0;" : "+l"(acc) : "l"(a), "l"(b));
}

// ---------------- CSR build -------------------------------------------------
__global__ void k_reset() {
    int t = blockIdx.x * 256 + threadIdx.x;
    if (t < NN) { g_deg[t] = 0; g_cur[t] = 0; }
}
__global__ void k_count(const int* __restrict__ eidx) {
    int e = blockIdx.x * 256 + threadIdx.x;
    if (e < EE) atomicAdd(&g_deg[eidx[EE + e]], 1);
}
__global__ void k_scan() {
    __shared__ int part[1024];
    int t = threadIdx.x;
    int base = t * 10;
    int s = 0;
    if (t < 1000)
        for (int i = 0; i < 10; i++) s += g_deg[base + i];
    part[t] = s;
    __syncthreads();
    for (int d = 1; d < 1024; d <<= 1) {
        int v = (t >= d) ? part[t - d] : 0;
        __syncthreads();
        part[t] += v;
        __syncthreads();
    }
    int excl = (t == 0) ? 0 : part[t - 1];
    if (t < 1000) {
        int run = excl;
        for (int i = 0; i < 10; i++) { g_off[base + i] = run; run += g_deg[base + i]; }
        if (t == 999) g_off[NN] = run;
    }
}
__global__ void k_fill(const int* __restrict__ eidx) {
    int e = blockIdx.x * 256 + threadIdx.x;
    if (e < EE) {
        int r = eidx[EE + e];
        int s = eidx[e];
        int pos = atomicAdd(&g_cur[r], 1);
        int slot = g_off[r] + pos;
        g_elist[slot] = e;
        g_slist[slot] = s;
    }
}

// ---------------- h = node_feats @ W_up ------------------------------------
#define H_SMEM ((128 * 128 + 32 * 128) * 4)
__global__ __launch_bounds__(256) void k_h(const float* __restrict__ feats,
                                           const float* __restrict__ Wup) {
    extern __shared__ float sm[];
    float* sW = sm;
    float* sF = sm + 16384;
    int n0 = blockIdx.x * 32;
    int t = threadIdx.x;
    for (int i = t; i < 16384; i += 256) sW[i] = Wup[i];
    for (int i = t; i < 4096; i += 256) {
        int n = n0 + (i >> 7);
        sF[i] = (n < NN) ? feats[n * CC + (i & 127)] : 0.f;
    }
    __syncthreads();
    int tk = (t & 31) * 4;
    int tn = (t >> 5) * 4;
    float acc[4][4] = {};
    for (int u = 0; u < 128; u++) {
        float4 b = *(const float4*)&sW[u * 128 + tk];
        #pragma unroll
        for (int i = 0; i < 4; i++) {
            float a = sF[(tn + i) * 128 + u];
            acc[i][0] = fmaf(a, b.x, acc[i][0]);
            acc[i][1] = fmaf(a, b.y, acc[i][1]);
            acc[i][2] = fmaf(a, b.z, acc[i][2]);
            acc[i][3] = fmaf(a, b.w, acc[i][3]);
        }
    }
    #pragma unroll
    for (int i = 0; i < 4; i++) {
        int n = n0 + tn + i;
        if (n < NN) {
            float4 v = make_float4(acc[i][0], acc[i][1], acc[i][2], acc[i][3]);
            *(float4*)&g_h[n * CC + tk] = v;
        }
    }
}

// ---------------- sc: 32 nodes x 256 threads (f32x2) — R8 proven form ------
#define SC_SMEM ((32 * 128 + 320 + 32 * 80 + 80 * 128) * 4)
__global__ __launch_bounds__(256) void k_sc(const float* __restrict__ feats,
                                            const float* __restrict__ attrs,
                                            const float* __restrict__ Wskip,
                                            float* __restrict__ sc_out) {
    extern __shared__ float sm[];
    float* sF = sm;
    float* sA = sF + 4096;
    float* sX = sA + 320;
    float* sW = sX + 2560;
    int n0 = blockIdx.x * 32;
    int t = threadIdx.x;
    for (int i = t; i < 4096; i += 256) {
        int n = n0 + (i >> 7);
        sF[i] = (n < NN) ? feats[n * CC + (i & 127)] : 0.f;
    }
    for (int i = t; i < 320; i += 256) {
        int n = n0 + i / 10;
        sA[i] = (n < NN) ? attrs[n * AA + i % 10] : 0.f;
    }
    int tk = (t & 31) * 4;
    int tn = (t >> 5) * 4;
    unsigned long long acc[4][2] = {};
    for (int uc = 0; uc < 16; uc++) {
        __syncthreads();
        for (int i = t; i < 10240; i += 256) sW[i] = Wskip[uc * 10240 + i];
        for (int idx = t; idx < 2560; idx += 256) {
            int n = idx / 80, i = idx % 80;
            sX[idx] = sF[n * 128 + uc * 8 + i / 10] * sA[n * 10 + i % 10];
        }
        __syncthreads();
        for (int i = 0; i < 80; i++) {
            ulonglong2 w = *(const ulonglong2*)&sW[i * 128 + tk];
            #pragma unroll
            for (int ii = 0; ii < 4; ii++) {
                float a = sX[(tn + ii) * 80 + i];
                unsigned long long A = pack2(a, a);
                ffma2(acc[ii][0], A, w.x);
                ffma2(acc[ii][1], A, w.y);
            }
        }
    }
    #pragma unroll
    for (int ii = 0; ii < 4; ii++) {
        int n = n0 + tn + ii;
        if (n < NN) {
            float f0, f1, f2, f3;
            unpack2(acc[ii][0], f0, f1);
            unpack2(acc[ii][1], f2, f3);
            *(float4*)&sc_out[n * CC + tk] = make_float4(f0, f1, f2, f3);
        }
    }
}

// ---------------- MLP layers 1-3 -------------------------------------------
#define MLP_SMEM ((512 + 4096 + 4096 + 512 + 4096 + 4096) * 4)
__global__ __launch_bounds__(256) void k_mlp123(const float* __restrict__ ef,
                                                const float* __restrict__ W1,
                                                const float* __restrict__ W2,
                                                const float* __restrict__ W3) {
    extern __shared__ float sm[];
    float* sW1 = sm;               // 512
    float* sW2 = sW1 + 512;        // 4096
    float* sW3 = sW2 + 4096;       // 4096
    float* sEF = sW3 + 4096;       // 512
    float* sTA = sEF + 512;        // 4096
    float* sTB = sTA + 4096;       // 4096
    float* sT3 = sEF;              // reuse (64*65=4160 <= 4608)
    int t = threadIdx.x;
    for (int i = t; i < 512; i += 256) sW1[i] = W1[i];
    for (int i = t; i < 4096; i += 256) sW2[i] = W2[i];
    for (int i = t; i < 4096; i += 256) sW3[i] = W3[i];
    int e0 = blockIdx.x * 64;
    for (int i = t; i < 512; i += 256) sEF[i] = ef[e0 * FF + i];
    __syncthreads();
    for (int o = t; o < 4096; o += 256) {
        int e = o >> 6, j = o & 63;
        float acc = 0.f;
        #pragma unroll
        for (int f = 0; f < 8; f++) acc = fmaf(sEF[e * 8 + f], sW1[f * 64 + j], acc);
        sTA[o] = silu(acc);
    }
    __syncthreads();
    int j0 = (t & 15) * 4, el = (t >> 4) * 4;
    {
        float acc[4][4] = {};
        for (int u = 0; u < 64; u++) {
            float4 b = *(const float4*)&sW2[u * 64 + j0];
            #pragma unroll
            for (int i = 0; i < 4; i++) {
                float a = sTA[(el + i) * 64 + u];
                acc[i][0] = fmaf(a, b.x, acc[i][0]);
                acc[i][1] = fmaf(a, b.y, acc[i][1]);
                acc[i][2] = fmaf(a, b.z, acc[i][2]);
                acc[i][3] = fmaf(a, b.w, acc[i][3]);
            }
        }
        #pragma unroll
        for (int i = 0; i < 4; i++)
            #pragma unroll
            for (int j = 0; j < 4; j++) sTB[(el + i) * 64 + j0 + j] = silu(acc[i][j]);
    }
    __syncthreads();
    {
        float acc[4][4] = {};
        for (int u = 0; u < 64; u++) {
            float4 b = *(const float4*)&sW3[u * 64 + j0];
            #pragma unroll
            for (int i = 0; i < 4; i++) {
                float a = sTB[(el + i) * 64 + u];
                acc[i][0] = fmaf(a, b.x, acc[i][0]);
                acc[i][1] = fmaf(a, b.y, acc[i][1]);
                acc[i][2] = fmaf(a, b.z, acc[i][2]);
                acc[i][3] = fmaf(a, b.w, acc[i][3]);
            }
        }
        #pragma unroll
        for (int i = 0; i < 4; i++)
            #pragma unroll
            for (int j = 0; j < 4; j++)
                sT3[(j0 + j) * 65 + el + i] = silu(acc[i][j]);
    }
    __syncthreads();
    for (int i = t; i < 4096; i += 256) {
        int u = i >> 6, e = i & 63;
        g_t3t[u * EE + e0 + e] = sT3[u * 65 + e];
    }
}

// ---------------- layer 4 GEMM: tpw[e] = T3[e] @ W4 (edge-major, R9) -------
#define G4_SMEM ((8192 + 8192) * 4)
__global__ __launch_bounds__(256) void k_gemm4(const float* __restrict__ W4) {
    extern __shared__ float sm[];
    float* sW = sm;            // 64 x 128 (this pass's j slice)
    float* sA = sm + 8192;     // 64 x 128
    int t = threadIdx.x;
    int e0 = blockIdx.x * 128;
    int jp = blockIdx.y * 128;
    for (int i = t; i < 8192; i += 256) {
        int u = i >> 7, j = i & 127;
        sW[i] = W4[u * 384 + jp + j];
    }
    for (int i = t; i < 2048; i += 256) {
        int u = i >> 5, e4 = (i & 31) * 4;
        *(float4*)&sA[u * 128 + e4] = *(const float4*)&g_t3t[u * EE + e0 + e4];
    }
    __syncthreads();
    int jg = t & 15, eg = t >> 4;
    int el = eg * 8, jb = jg * 8;
    unsigned long long acc[8][4] = {};
    #pragma unroll 4
    for (int u = 0; u < 64; u++) {
        float4 a03 = *(const float4*)&sA[u * 128 + el];
        float4 a47 = *(const float4*)&sA[u * 128 + el + 4];
        ulonglong2 wA = *(const ulonglong2*)&sW[u * 128 + jb];
        ulonglong2 wB = *(const ulonglong2*)&sW[u * 128 + jb + 4];
        unsigned long long A0 = pack2(a03.x, a03.x);
        unsigned long long A1 = pack2(a03.y, a03.y);
        unsigned long long A2 = pack2(a03.z, a03.z);
        unsigned long long A3 = pack2(a03.w, a03.w);
        unsigned long long A4 = pack2(a47.x, a47.x);
        unsigned long long A5 = pack2(a47.y, a47.y);
        unsigned long long A6 = pack2(a47.z, a47.z);
        unsigned long long A7 = pack2(a47.w, a47.w);
        ffma2(acc[0][0], A0, wA.x); ffma2(acc[0][1], A0, wA.y);
        ffma2(acc[0][2], A0, wB.x); ffma2(acc[0][3], A0, wB.y);
        ffma2(acc[1][0], A1, wA.x); ffma2(acc[1][1], A1, wA.y);
        ffma2(acc[1][2], A1, wB.x); ffma2(acc[1][3], A1, wB.y);
        ffma2(acc[2][0], A2, wA.x); ffma2(acc[2][1], A2, wA.y);
        ffma2(acc[2][2], A2, wB.x); ffma2(acc[2][3], A2, wB.y);
        ffma2(acc[3][0], A3, wA.x); ffma2(acc[3][1], A3, wA.y);
        ffma2(acc[3][2], A3, wB.x); ffma2(acc[3][3], A3, wB.y);
        ffma2(acc[4][0], A4, wA.x); ffma2(acc[4][1], A4, wA.y);
        ffma2(acc[4][2], A4, wB.x); ffma2(acc[4][3], A4, wB.y);
        ffma2(acc[5][0], A5, wA.x); ffma2(acc[5][1], A5, wA.y);
        ffma2(acc[5][2], A5, wB.x); ffma2(acc[5][3], A5, wB.y);
        ffma2(acc[6][0], A6, wA.x); ffma2(acc[6][1], A6, wA.y);
        ffma2(acc[6][2], A6, wB.x); ffma2(acc[6][3], A6, wB.y);
        ffma2(acc[7][0], A7, wA.x); ffma2(acc[7][1], A7, wA.y);
        ffma2(acc[7][2], A7, wB.x); ffma2(acc[7][3], A7, wB.y);
    }
    #pragma unroll
    for (int i = 0; i < 8; i++) {
        float f0, f1, f2, f3, f4, f5, f6, f7;
        unpack2(acc[i][0], f0, f1);
        unpack2(acc[i][1], f2, f3);
        unpack2(acc[i][2], f4, f5);
        unpack2(acc[i][3], f6, f7);
        long base = (long)(e0 + el + i) * 384 + jp + jb;
        *(float4*)&g_tpw[base]     = make_float4(f0, f1, f2, f3);
        *(float4*)&g_tpw[base + 4] = make_float4(f4, f5, f6, f7);
    }
}

// ---------------- gather: 4-edge software pipeline -------------------------
// 1 warp per node, 4 channels/thread. Batch 4 edges: all index loads first,
// then all 16 vector loads, then accumulate. 4x memory-level parallelism,
// zero extra traffic. 8 nodes / 256-thread block.
struct EdgeVec {
    float4 x, t0, t1, t2;
};
__device__ __forceinline__ void g_accum(const EdgeVec& v, int e,
                                        const float* __restrict__ yr,
                                        const float* __restrict__ yi,
                                        float4* ar, float4* ai) {
    float4 xw0 = make_float4(v.x.x * v.t0.x, v.x.y * v.t0.y, v.x.z * v.t0.z, v.x.w * v.t0.w);
    float4 xw1 = make_float4(v.x.x * v.t1.x, v.x.y * v.t1.y, v.x.z * v.t1.z, v.x.w * v.t1.w);
    float4 xw2 = make_float4(v.x.x * v.t2.x, v.x.y * v.t2.y, v.x.z * v.t2.z, v.x.w * v.t2.w);
    const float* yre = yr + e * 9;
    const float* yie = yi + e * 9;
    #pragma unroll
    for (int m = 0; m < 9; m++) {
        float4 xw = (m == 0) ? xw0 : (m < 4) ? xw1 : xw2;
        float vr = yre[m], vi = yie[m];
        ar[m].x = fmaf(xw.x, vr, ar[m].x); ar[m].y = fmaf(xw.y, vr, ar[m].y);
        ar[m].z = fmaf(xw.z, vr, ar[m].z); ar[m].w = fmaf(xw.w, vr, ar[m].w);
        ai[m].x = fmaf(xw.x, vi, ai[m].x); ai[m].y = fmaf(xw.y, vi, ai[m].y);
        ai[m].z = fmaf(xw.z, vi, ai[m].z); ai[m].w = fmaf(xw.w, vi, ai[m].w);
    }
}
__device__ __forceinline__ void g_load(EdgeVec& v, int e, int s, int c0) {
    v.x  = *(const float4*)&g_h[s * CC + c0];
    const float* tw = g_tpw + (long)e * 384;
    v.t0 = *(const float4*)&tw[c0];
    v.t1 = *(const float4*)&tw[128 + c0];
    v.t2 = *(const float4*)&tw[256 + c0];
}
__global__ __launch_bounds__(256) void k_gather(const float* __restrict__ yr,
                                                const float* __restrict__ yi) {
    int t = threadIdx.x;
    int n = blockIdx.x * 8 + (t >> 5);
    int c0 = (t & 31) * 4;
    float4 ar[9], ai[9];
    #pragma unroll
    for (int m = 0; m < 9; m++) {
        ar[m] = make_float4(0.f, 0.f, 0.f, 0.f);
        ai[m] = make_float4(0.f, 0.f, 0.f, 0.f);
    }
    int beg = g_off[n], end = g_off[n + 1];
    int i = beg;
    for (; i + 4 <= end; i += 4) {
        // batch index loads (consecutive, independent)
        int ea = g_elist[i],     eb = g_elist[i + 1];
        int ec = g_elist[i + 2], ed = g_elist[i + 3];
        int sa = g_slist[i],     sb = g_slist[i + 1];
        int sc2 = g_slist[i + 2], sd = g_slist[i + 3];
        // batch all 16 vector loads before any consumption
        EdgeVec va, vb, vc, vd;
        g_load(va, ea, sa, c0);
        g_load(vb, eb, sb, c0);
        g_load(vc, ec, sc2, c0);
        g_load(vd, ed, sd, c0);
        g_accum(va, ea, yr, yi, ar, ai);
        g_accum(vb, eb, yr, yi, ar, ai);
        g_accum(vc, ec, yr, yi, ar, ai);
        g_accum(vd, ed, yr, yi, ar, ai);
    }
    for (; i < end; i++) {
        int e = g_elist[i];
        int s = g_slist[i];
        EdgeVec v;
        g_load(v, e, s, c0);
        g_accum(v, e, yr, yi, ar, ai);
    }
    float* mr = g_msg_r + n * MSGW;
    float* mi = g_msg_i + n * MSGW;
    *(float4*)&mr[c0] = ar[0];
    *(float4*)&mi[c0] = ai[0];
    #pragma unroll
    for (int m = 0; m < 3; m++) {
        *(float4*)&mr[128 + m * 128 + c0] = ar[1 + m];
        *(float4*)&mi[128 + m * 128 + c0] = ai[1 + m];
    }
    #pragma unroll
    for (int m = 0; m < 5; m++) {
        *(float4*)&mr[512 + m * 128 + c0] = ar[4 + m];
        *(float4*)&mi[512 + m * 128 + c0] = ai[4 + m];
    }
}

// ---------------- linear_irreps: in-place writeback into g_msg -------------
#define LIN_SMEM ((128 * 128 + 2 * 32 * 128) * 4)
__global__ __launch_bounds__(256) void k_linear(const float* __restrict__ W,
                                                int d, int loff) {
    extern __shared__ float sm[];
    float* sW  = sm;
    float* sAr = sm + 16384;
    float* sAi = sAr + 4096;
    int nrows = NN * d;
    int t = threadIdx.x;
    for (int i = t; i < 16384; i += 256) sW[i] = W[i];
    int tk = (t & 31) * 4;
    int tr = (t >> 5) * 4;
    for (int r0 = blockIdx.x * 32; r0 < nrows; r0 += gridDim.x * 32) {
        __syncthreads();
        for (int i = t; i < 4096; i += 256) {
            int rl = i >> 7, u = i & 127;
            int row = r0 + rl;
            float vr = 0.f, vi = 0.f;
            if (row < nrows) {
                int n = row / d, m = row % d;
                int off = n * MSGW + loff + m * 128 + u;
                vr = g_msg_r[off];
                vi = g_msg_i[off];
            }
            sAr[i] = vr;
            sAi[i] = vi;
        }
        __syncthreads();
        unsigned long long accr[4][2] = {};
        unsigned long long acci[4][2] = {};
        for (int u = 0; u < 128; u++) {
            ulonglong2 w = *(const ulonglong2*)&sW[u * 128 + tk];
            #pragma unroll
            for (int i = 0; i < 4; i++) {
                float a = sAr[(tr + i) * 128 + u];
                unsigned long long A = pack2(a, a);
                ffma2(accr[i][0], A, w.x);
                ffma2(accr[i][1], A, w.y);
                float c = sAi[(tr + i) * 128 + u];
                unsigned long long Cc = pack2(c, c);
                ffma2(acci[i][0], Cc, w.x);
                ffma2(acci[i][1], Cc, w.y);
            }
        }
        #pragma unroll
        for (int i = 0; i < 4; i++) {
            int row = r0 + tr + i;
            if (row < nrows) {
                int n = row / d, m = row % d;
                int off = n * MSGW + loff + m * 128 + tk;
                float r01[4], i01[4];
                unpack2(accr[i][0], r01[0], r01[1]);
                unpack2(accr[i][1], r01[2], r01[3]);
                unpack2(acci[i][0], i01[0], i01[1]);
                unpack2(acci[i][1], i01[2], i01[3]);
                *(float4*)&g_msg_r[off] = make_float4(r01[0], r01[1], r01[2], r01[3]);
                *(float4*)&g_msg_i[off] = make_float4(i01[0], i01[1], i01[2], i01[3]);
            }
        }
    }
}

// ---------------- transpose [mo*128+k] -> [k*9+mo] per node ----------------
__global__ __launch_bounds__(256) void k_transpose(float* __restrict__ out_r,
                                                   float* __restrict__ out_i) {
    __shared__ float sr[8 * MSGW];
    __shared__ float si[8 * MSGW];
    int t = threadIdx.x;
    int n0 = blockIdx.x * 8;
    for (int i = t; i < 2304; i += 256) {
        int nd = i / 288, o4 = (i % 288) * 4;
        *(float4*)&sr[nd * MSGW + o4] = *(const float4*)&g_msg_r[(n0 + nd) * MSGW + o4];
        *(float4*)&si[nd * MSGW + o4] = *(const float4*)&g_msg_i[(n0 + nd) * MSGW + o4];
    }
    __syncthreads();
    for (int i = t; i < 2304; i += 256) {
        int nd = i / 288, o4 = (i % 288) * 4;
        const float* br = sr + nd * MSGW;
        const float* bi = si + nd * MSGW;
        float vr[4], vi[4];
        #pragma unroll
        for (int c = 0; c < 4; c++) {
            int oidx = o4 + c;
            int k = oidx / 9;
            int mo = oidx - 9 * k;
            vr[c] = br[mo * 128 + k];
            vi[c] = bi[mo * 128 + k];
        }
        long ob = (long)(n0 + nd) * MSGW + o4;
        *(float4*)&out_r[ob] = make_float4(vr[0], vr[1], vr[2], vr[3]);
        *(float4*)&out_i[ob] = make_float4(vi[0], vi[1], vi[2], vi[3]);
    }
}

// ---------------- launch ---------------------------------------------------
extern "C" void kernel_launch(void* const* d_in, const int* in_sizes, int n_in,
                              void* d_out, int out_size) {
    const float* node_attrs = (const float*)d_in[0];
    const float* node_feats = (const float*)d_in[1];
    const float* yr        = (const float*)d_in[2];
    const float* yi        = (const float*)d_in[3];
    const float* ef        = (const float*)d_in[4];
    const int*   eidx      = (const int*)  d_in[5];
    const float* Wup       = (const float*)d_in[6];
    const float* Wskip     = (const float*)d_in[7];
    const float* W1        = (const float*)d_in[8];
    const float* W2        = (const float*)d_in[9];
    const float* W3        = (const float*)d_in[10];
    const float* W4        = (const float*)d_in[11];
    const float* Wl0       = (const float*)d_in[12];
    const float* Wl1       = (const float*)d_in[13];
    const float* Wl2       = (const float*)d_in[14];

    float* out   = (float*)d_out;
    float* out_r = out;
    float* out_i = out + OUTR_ELEMS;
    float* out_s = out + 2 * OUTR_ELEMS;

    cudaFuncSetAttribute(k_h,      cudaFuncAttributeMaxDynamicSharedMemorySize, H_SMEM);
    cudaFuncSetAttribute(k_sc,     cudaFuncAttributeMaxDynamicSharedMemorySize, SC_SMEM);
    cudaFuncSetAttribute(k_mlp123, cudaFuncAttributeMaxDynamicSharedMemorySize, MLP_SMEM);
    cudaFuncSetAttribute(k_gemm4,  cudaFuncAttributeMaxDynamicSharedMemorySize, G4_SMEM);
    cudaFuncSetAttribute(k_linear, cudaFuncAttributeMaxDynamicSharedMemorySize, LIN_SMEM);

    // idx 0..2
    k_reset<<<(NN + 255) / 256, 256>>>();
    k_count<<<(EE + 255) / 256, 256>>>(eidx);
    k_scan<<<1, 1024>>>();
    // idx 3: profiled launch (k_h — last unmeasured kernel)
    k_h<<<(NN + 31) / 32, 256, H_SMEM>>>(node_feats, Wup);
    // idx 4..7
    k_fill<<<(EE + 255) / 256, 256>>>(eidx);
    k_mlp123<<<EE / 64, 256, MLP_SMEM>>>(ef, W1, W2, W3);
    k_sc<<<(NN + 31) / 32, 256, SC_SMEM>>>(node_feats, node_attrs, Wskip, out_s);
    k_gemm4<<<dim3(EE / 128, 3), 256, G4_SMEM>>>(W4);
    // idx 8
    k_gather<<<NN / 8, 256>>>(yr, yi);
    // idx 9..11: linear (in-place writeback into g_msg)
    k_linear<<<296, 256, LIN_SMEM>>>(Wl0, 1, 0);
    k_linear<<<296, 256, LIN_SMEM>>>(Wl1, 3, 128);
    k_linear<<<296, 256, LIN_SMEM>>>(Wl2, 5, 512);
    // idx 12: layout transpose to out
    k_transpose<<<NN / 8, 256>>>(out_r, out_i);
}

// round 14
// speedup vs baseline: 1.2803x; 1.2490x over previous
#include <cuda_runtime.h>
#include <cuda_bf16.h>
#include <cstdint>

// Problem constants
#define NN 10000
#define EE 128000
#define CC 128
#define AA 10
#define FF 8
#define MSGW 1152
#define OUTR_ELEMS (NN * CC * 9)

// ---------------- scratch (device globals) ---------------------------------
__device__ float g_h[NN * CC];
__device__ float g_tpw[(long)EE * 384];
__device__ float g_msg_r[NN * MSGW];
__device__ float g_msg_i[NN * MSGW];
__device__ int   g_deg[NN];
__device__ int   g_cur[NN];
__device__ int   g_off[NN + 1];
__device__ int   g_elist[EE];
__device__ int   g_slist[EE];
__device__ float g_t3t[64 * EE];          // T3 transposed [u][e]

__device__ __forceinline__ float silu(float x) {
    return x * (1.0f / (1.0f + __expf(-x)));
}

// f32x2 packed helpers
__device__ __forceinline__ unsigned long long pack2(float lo, float hi) {
    unsigned long long r;
    asm("mov.b64 %0, {%1, %2};" : "=l"(r) : "f"(lo), "f"(hi));
    return r;
}
__device__ __forceinline__ void unpack2(unsigned long long v, float& lo, float& hi) {
    asm("mov.b64 {%0, %1}, %2;" : "=f"(lo), "=f"(hi) : "l"(v));
}
__device__ __forceinline__ void ffma2(unsigned long long& acc,
                                      unsigned long long a, unsigned long long b) {
    asm("fma.rn.f32x2 %0, %1, %2, %0;" : "+l"(acc) : "l"(a), "l"(b));
}

// ---------------- CSR build -------------------------------------------------
__global__ void k_reset() {
    int t = blockIdx.x * 256 + threadIdx.x;
    if (t < NN) { g_deg[t] = 0; g_cur[t] = 0; }
}
__global__ void k_count(const int* __restrict__ eidx) {
    int e = blockIdx.x * 256 + threadIdx.x;
    if (e < EE) atomicAdd(&g_deg[eidx[EE + e]], 1);
}
__global__ void k_scan() {
    __shared__ int part[1024];
    int t = threadIdx.x;
    int base = t * 10;
    int s = 0;
    if (t < 1000)
        for (int i = 0; i < 10; i++) s += g_deg[base + i];
    part[t] = s;
    __syncthreads();
    for (int d = 1; d < 1024; d <<= 1) {
        int v = (t >= d) ? part[t - d] : 0;
        __syncthreads();
        part[t] += v;
        __syncthreads();
    }
    int excl = (t == 0) ? 0 : part[t - 1];
    if (t < 1000) {
        int run = excl;
        for (int i = 0; i < 10; i++) { g_off[base + i] = run; run += g_deg[base + i]; }
        if (t == 999) g_off[NN] = run;
    }
}
__global__ void k_fill(const int* __restrict__ eidx) {
    int e = blockIdx.x * 256 + threadIdx.x;
    if (e < EE) {
        int r = eidx[EE + e];
        int s = eidx[e];
        int pos = atomicAdd(&g_cur[r], 1);
        int slot = g_off[r] + pos;
        g_elist[slot] = e;
        g_slist[slot] = s;
    }
}

// ---------------- h = node_feats @ W_up (float4 staging) --------------------
#define H_SMEM ((128 * 128 + 32 * 128) * 4)
__global__ __launch_bounds__(256) void k_h(const float* __restrict__ feats,
                                           const float* __restrict__ Wup) {
    extern __shared__ float sm[];
    float* sW = sm;
    float* sF = sm + 16384;
    int n0 = blockIdx.x * 32;
    int t = threadIdx.x;
    for (int i4 = t * 4; i4 < 16384; i4 += 1024)
        *(float4*)&sW[i4] = *(const float4*)&Wup[i4];
    for (int i4 = t * 4; i4 < 4096; i4 += 1024) {
        int n = n0 + (i4 >> 7);
        float4 v = make_float4(0.f, 0.f, 0.f, 0.f);
        if (n < NN) v = *(const float4*)&feats[n * CC + (i4 & 127)];
        *(float4*)&sF[i4] = v;
    }
    __syncthreads();
    int tk = (t & 31) * 4;
    int tn = (t >> 5) * 4;
    float acc[4][4] = {};
    for (int u = 0; u < 128; u++) {
        float4 b = *(const float4*)&sW[u * 128 + tk];
        #pragma unroll
        for (int i = 0; i < 4; i++) {
            float a = sF[(tn + i) * 128 + u];
            acc[i][0] = fmaf(a, b.x, acc[i][0]);
            acc[i][1] = fmaf(a, b.y, acc[i][1]);
            acc[i][2] = fmaf(a, b.z, acc[i][2]);
            acc[i][3] = fmaf(a, b.w, acc[i][3]);
        }
    }
    #pragma unroll
    for (int i = 0; i < 4; i++) {
        int n = n0 + tn + i;
        if (n < NN) {
            float4 v = make_float4(acc[i][0], acc[i][1], acc[i][2], acc[i][3]);
            *(float4*)&g_h[n * CC + tk] = v;
        }
    }
}

// ---------------- sc: 32 nodes x 256 threads, float4 W staging --------------
#define SC_SMEM ((32 * 128 + 320 + 32 * 80 + 80 * 128) * 4)
__global__ __launch_bounds__(256) void k_sc(const float* __restrict__ feats,
                                            const float* __restrict__ attrs,
                                            const float* __restrict__ Wskip,
                                            float* __restrict__ sc_out) {
    extern __shared__ float sm[];
    float* sF = sm;
    float* sA = sF + 4096;
    float* sX = sA + 320;
    float* sW = sX + 2560;
    int n0 = blockIdx.x * 32;
    int t = threadIdx.x;
    for (int i4 = t * 4; i4 < 4096; i4 += 1024) {
        int n = n0 + (i4 >> 7);
        float4 v = make_float4(0.f, 0.f, 0.f, 0.f);
        if (n < NN) v = *(const float4*)&feats[n * CC + (i4 & 127)];
        *(float4*)&sF[i4] = v;
    }
    for (int i = t; i < 320; i += 256) {
        int n = n0 + i / 10;
        sA[i] = (n < NN) ? attrs[n * AA + i % 10] : 0.f;
    }
    int tk = (t & 31) * 4;
    int tn = (t >> 5) * 4;
    unsigned long long acc[4][2] = {};
    for (int uc = 0; uc < 16; uc++) {
        __syncthreads();
        for (int i4 = t * 4; i4 < 10240; i4 += 1024)
            *(float4*)&sW[i4] = *(const float4*)&Wskip[uc * 10240 + i4];
        for (int idx = t; idx < 2560; idx += 256) {
            int n = idx / 80, i = idx % 80;
            sX[idx] = sF[n * 128 + uc * 8 + i / 10] * sA[n * 10 + i % 10];
        }
        __syncthreads();
        for (int i = 0; i < 80; i++) {
            ulonglong2 w = *(const ulonglong2*)&sW[i * 128 + tk];
            #pragma unroll
            for (int ii = 0; ii < 4; ii++) {
                float a = sX[(tn + ii) * 80 + i];
                unsigned long long A = pack2(a, a);
                ffma2(acc[ii][0], A, w.x);
                ffma2(acc[ii][1], A, w.y);
            }
        }
    }
    #pragma unroll
    for (int ii = 0; ii < 4; ii++) {
        int n = n0 + tn + ii;
        if (n < NN) {
            float f0, f1, f2, f3;
            unpack2(acc[ii][0], f0, f1);
            unpack2(acc[ii][1], f2, f3);
            *(float4*)&sc_out[n * CC + tk] = make_float4(f0, f1, f2, f3);
        }
    }
}

// ---------------- MLP layers 1-3 (float4 W staging) -------------------------
#define MLP_SMEM ((512 + 4096 + 4096 + 512 + 4096 + 4096) * 4)
__global__ __launch_bounds__(256) void k_mlp123(const float* __restrict__ ef,
                                                const float* __restrict__ W1,
                                                const float* __restrict__ W2,
                                                const float* __restrict__ W3) {
    extern __shared__ float sm[];
    float* sW1 = sm;               // 512
    float* sW2 = sW1 + 512;        // 4096
    float* sW3 = sW2 + 4096;       // 4096
    float* sEF = sW3 + 4096;       // 512
    float* sTA = sEF + 512;        // 4096
    float* sTB = sTA + 4096;       // 4096
    float* sT3 = sEF;              // reuse (64*65=4160 <= 4608)
    int t = threadIdx.x;
    for (int i4 = t * 4; i4 < 512; i4 += 1024)
        *(float4*)&sW1[i4] = *(const float4*)&W1[i4];
    for (int i4 = t * 4; i4 < 4096; i4 += 1024) {
        *(float4*)&sW2[i4] = *(const float4*)&W2[i4];
        *(float4*)&sW3[i4] = *(const float4*)&W3[i4];
    }
    int e0 = blockIdx.x * 64;
    for (int i4 = t * 4; i4 < 512; i4 += 1024)
        *(float4*)&sEF[i4] = *(const float4*)&ef[e0 * FF + i4];
    __syncthreads();
    for (int o = t; o < 4096; o += 256) {
        int e = o >> 6, j = o & 63;
        float acc = 0.f;
        #pragma unroll
        for (int f = 0; f < 8; f++) acc = fmaf(sEF[e * 8 + f], sW1[f * 64 + j], acc);
        sTA[o] = silu(acc);
    }
    __syncthreads();
    int j0 = (t & 15) * 4, el = (t >> 4) * 4;
    {
        float acc[4][4] = {};
        for (int u = 0; u < 64; u++) {
            float4 b = *(const float4*)&sW2[u * 64 + j0];
            #pragma unroll
            for (int i = 0; i < 4; i++) {
                float a = sTA[(el + i) * 64 + u];
                acc[i][0] = fmaf(a, b.x, acc[i][0]);
                acc[i][1] = fmaf(a, b.y, acc[i][1]);
                acc[i][2] = fmaf(a, b.z, acc[i][2]);
                acc[i][3] = fmaf(a, b.w, acc[i][3]);
            }
        }
        #pragma unroll
        for (int i = 0; i < 4; i++)
            #pragma unroll
            for (int j = 0; j < 4; j++) sTB[(el + i) * 64 + j0 + j] = silu(acc[i][j]);
    }
    __syncthreads();
    {
        float acc[4][4] = {};
        for (int u = 0; u < 64; u++) {
            float4 b = *(const float4*)&sW3[u * 64 + j0];
            #pragma unroll
            for (int i = 0; i < 4; i++) {
                float a = sTB[(el + i) * 64 + u];
                acc[i][0] = fmaf(a, b.x, acc[i][0]);
                acc[i][1] = fmaf(a, b.y, acc[i][1]);
                acc[i][2] = fmaf(a, b.z, acc[i][2]);
                acc[i][3] = fmaf(a, b.w, acc[i][3]);
            }
        }
        #pragma unroll
        for (int i = 0; i < 4; i++)
            #pragma unroll
            for (int j = 0; j < 4; j++)
                sT3[(j0 + j) * 65 + el + i] = silu(acc[i][j]);
    }
    __syncthreads();
    for (int i = t; i < 4096; i += 256) {
        int u = i >> 6, e = i & 63;
        g_t3t[u * EE + e0 + e] = sT3[u * 65 + e];
    }
}

// ---------------- layer 4 GEMM: tpw[e] = T3[e] @ W4 -------------------------
#define G4_SMEM ((8192 + 8192) * 4)
__global__ __launch_bounds__(256) void k_gemm4(const float* __restrict__ W4) {
    extern __shared__ float sm[];
    float* sW = sm;            // 64 x 128 (this pass's j slice)
    float* sA = sm + 8192;     // 64 x 128
    int t = threadIdx.x;
    int e0 = blockIdx.x * 128;
    int jp = blockIdx.y * 128;
    for (int i4 = t * 4; i4 < 8192; i4 += 1024) {
        int u = i4 >> 7, j = i4 & 127;
        *(float4*)&sW[i4] = *(const float4*)&W4[u * 384 + jp + j];
    }
    for (int i = t; i < 2048; i += 256) {
        int u = i >> 5, e4 = (i & 31) * 4;
        *(float4*)&sA[u * 128 + e4] = *(const float4*)&g_t3t[u * EE + e0 + e4];
    }
    __syncthreads();
    int jg = t & 15, eg = t >> 4;
    int el = eg * 8, jb = jg * 8;
    unsigned long long acc[8][4] = {};
    #pragma unroll 4
    for (int u = 0; u < 64; u++) {
        float4 a03 = *(const float4*)&sA[u * 128 + el];
        float4 a47 = *(const float4*)&sA[u * 128 + el + 4];
        ulonglong2 wA = *(const ulonglong2*)&sW[u * 128 + jb];
        ulonglong2 wB = *(const ulonglong2*)&sW[u * 128 + jb + 4];
        unsigned long long A0 = pack2(a03.x, a03.x);
        unsigned long long A1 = pack2(a03.y, a03.y);
        unsigned long long A2 = pack2(a03.z, a03.z);
        unsigned long long A3 = pack2(a03.w, a03.w);
        unsigned long long A4 = pack2(a47.x, a47.x);
        unsigned long long A5 = pack2(a47.y, a47.y);
        unsigned long long A6 = pack2(a47.z, a47.z);
        unsigned long long A7 = pack2(a47.w, a47.w);
        ffma2(acc[0][0], A0, wA.x); ffma2(acc[0][1], A0, wA.y);
        ffma2(acc[0][2], A0, wB.x); ffma2(acc[0][3], A0, wB.y);
        ffma2(acc[1][0], A1, wA.x); ffma2(acc[1][1], A1, wA.y);
        ffma2(acc[1][2], A1, wB.x); ffma2(acc[1][3], A1, wB.y);
        ffma2(acc[2][0], A2, wA.x); ffma2(acc[2][1], A2, wA.y);
        ffma2(acc[2][2], A2, wB.x); ffma2(acc[2][3], A2, wB.y);
        ffma2(acc[3][0], A3, wA.x); ffma2(acc[3][1], A3, wA.y);
        ffma2(acc[3][2], A3, wB.x); ffma2(acc[3][3], A3, wB.y);
        ffma2(acc[4][0], A4, wA.x); ffma2(acc[4][1], A4, wA.y);
        ffma2(acc[4][2], A4, wB.x); ffma2(acc[4][3], A4, wB.y);
        ffma2(acc[5][0], A5, wA.x); ffma2(acc[5][1], A5, wA.y);
        ffma2(acc[5][2], A5, wB.x); ffma2(acc[5][3], A5, wB.y);
        ffma2(acc[6][0], A6, wA.x); ffma2(acc[6][1], A6, wA.y);
        ffma2(acc[6][2], A6, wB.x); ffma2(acc[6][3], A6, wB.y);
        ffma2(acc[7][0], A7, wA.x); ffma2(acc[7][1], A7, wA.y);
        ffma2(acc[7][2], A7, wB.x); ffma2(acc[7][3], A7, wB.y);
    }
    #pragma unroll
    for (int i = 0; i < 8; i++) {
        float f0, f1, f2, f3, f4, f5, f6, f7;
        unpack2(acc[i][0], f0, f1);
        unpack2(acc[i][1], f2, f3);
        unpack2(acc[i][2], f4, f5);
        unpack2(acc[i][3], f6, f7);
        long base = (long)(e0 + el + i) * 384 + jp + jb;
        *(float4*)&g_tpw[base]     = make_float4(f0, f1, f2, f3);
        *(float4*)&g_tpw[base + 4] = make_float4(f4, f5, f6, f7);
    }
}

// ---------------- gather: exact R9 form (proven local optimum) --------------
__global__ __launch_bounds__(256) void k_gather(const float* __restrict__ yr,
                                                const float* __restrict__ yi) {
    int t = threadIdx.x;
    int n = blockIdx.x * 8 + (t >> 5);
    int c0 = (t & 31) * 4;
    float4 ar[9], ai[9];
    #pragma unroll
    for (int m = 0; m < 9; m++) {
        ar[m] = make_float4(0.f, 0.f, 0.f, 0.f);
        ai[m] = make_float4(0.f, 0.f, 0.f, 0.f);
    }
    int beg = g_off[n], end = g_off[n + 1];
    #pragma unroll 2
    for (int i = beg; i < end; i++) {
        int e = g_elist[i];
        int s = g_slist[i];
        float4 x  = *(const float4*)&g_h[s * CC + c0];
        const float* tw = g_tpw + (long)e * 384;
        float4 t0 = *(const float4*)&tw[c0];
        float4 t1 = *(const float4*)&tw[128 + c0];
        float4 t2 = *(const float4*)&tw[256 + c0];
        float4 xw0 = make_float4(x.x * t0.x, x.y * t0.y, x.z * t0.z, x.w * t0.w);
        float4 xw1 = make_float4(x.x * t1.x, x.y * t1.y, x.z * t1.z, x.w * t1.w);
        float4 xw2 = make_float4(x.x * t2.x, x.y * t2.y, x.z * t2.z, x.w * t2.w);
        const float* yre = yr + e * 9;
        const float* yie = yi + e * 9;
        #pragma unroll
        for (int m = 0; m < 9; m++) {
            float4 xw = (m == 0) ? xw0 : (m < 4) ? xw1 : xw2;
            float vr = yre[m], vi = yie[m];
            ar[m].x = fmaf(xw.x, vr, ar[m].x); ar[m].y = fmaf(xw.y, vr, ar[m].y);
            ar[m].z = fmaf(xw.z, vr, ar[m].z); ar[m].w = fmaf(xw.w, vr, ar[m].w);
            ai[m].x = fmaf(xw.x, vi, ai[m].x); ai[m].y = fmaf(xw.y, vi, ai[m].y);
            ai[m].z = fmaf(xw.z, vi, ai[m].z); ai[m].w = fmaf(xw.w, vi, ai[m].w);
        }
    }
    float* mr = g_msg_r + n * MSGW;
    float* mi = g_msg_i + n * MSGW;
    *(float4*)&mr[c0] = ar[0];
    *(float4*)&mi[c0] = ai[0];
    #pragma unroll
    for (int m = 0; m < 3; m++) {
        *(float4*)&mr[128 + m * 128 + c0] = ar[1 + m];
        *(float4*)&mi[128 + m * 128 + c0] = ai[1 + m];
    }
    #pragma unroll
    for (int m = 0; m < 5; m++) {
        *(float4*)&mr[512 + m * 128 + c0] = ar[4 + m];
        *(float4*)&mi[512 + m * 128 + c0] = ai[4 + m];
    }
}

// ---------------- linear_irreps: in-place writeback into g_msg -------------
#define LIN_SMEM ((128 * 128 + 2 * 32 * 128) * 4)
__global__ __launch_bounds__(256) void k_linear(const float* __restrict__ W,
                                                int d, int loff) {
    extern __shared__ float sm[];
    float* sW  = sm;
    float* sAr = sm + 16384;
    float* sAi = sAr + 4096;
    int nrows = NN * d;
    int t = threadIdx.x;
    for (int i4 = t * 4; i4 < 16384; i4 += 1024)
        *(float4*)&sW[i4] = *(const float4*)&W[i4];
    int tk = (t & 31) * 4;
    int tr = (t >> 5) * 4;
    for (int r0 = blockIdx.x * 32; r0 < nrows; r0 += gridDim.x * 32) {
        __syncthreads();
        for (int i4 = t * 4; i4 < 4096; i4 += 1024) {
            int rl = i4 >> 7, u = i4 & 127;
            int row = r0 + rl;
            float4 vr = make_float4(0.f, 0.f, 0.f, 0.f);
            float4 vi = make_float4(0.f, 0.f, 0.f, 0.f);
            if (row < nrows) {
                int n = row / d, m = row % d;
                int off = n * MSGW + loff + m * 128 + u;
                vr = *(const float4*)&g_msg_r[off];
                vi = *(const float4*)&g_msg_i[off];
            }
            *(float4*)&sAr[i4] = vr;
            *(float4*)&sAi[i4] = vi;
        }
        __syncthreads();
        unsigned long long accr[4][2] = {};
        unsigned long long acci[4][2] = {};
        for (int u = 0; u < 128; u++) {
            ulonglong2 w = *(const ulonglong2*)&sW[u * 128 + tk];
            #pragma unroll
            for (int i = 0; i < 4; i++) {
                float a = sAr[(tr + i) * 128 + u];
                unsigned long long A = pack2(a, a);
                ffma2(accr[i][0], A, w.x);
                ffma2(accr[i][1], A, w.y);
                float c = sAi[(tr + i) * 128 + u];
                unsigned long long Cc = pack2(c, c);
                ffma2(acci[i][0], Cc, w.x);
                ffma2(acci[i][1], Cc, w.y);
            }
        }
        #pragma unroll
        for (int i = 0; i < 4; i++) {
            int row = r0 + tr + i;
            if (row < nrows) {
                int n = row / d, m = row % d;
                int off = n * MSGW + loff + m * 128 + tk;
                float r01[4], i01[4];
                unpack2(accr[i][0], r01[0], r01[1]);
                unpack2(accr[i][1], r01[2], r01[3]);
                unpack2(acci[i][0], i01[0], i01[1]);
                unpack2(acci[i][1], i01[2], i01[3]);
                *(float4*)&g_msg_r[off] = make_float4(r01[0], r01[1], r01[2], r01[3]);
                *(float4*)&g_msg_i[off] = make_float4(i01[0], i01[1], i01[2], i01[3]);
            }
        }
    }
}

// ---------------- transpose [mo*128+k] -> [k*9+mo] per node ----------------
__global__ __launch_bounds__(256) void k_transpose(float* __restrict__ out_r,
                                                   float* __restrict__ out_i) {
    __shared__ float sr[8 * MSGW];
    __shared__ float si[8 * MSGW];
    int t = threadIdx.x;
    int n0 = blockIdx.x * 8;
    for (int i = t; i < 2304; i += 256) {
        int nd = i / 288, o4 = (i % 288) * 4;
        *(float4*)&sr[nd * MSGW + o4] = *(const float4*)&g_msg_r[(n0 + nd) * MSGW + o4];
        *(float4*)&si[nd * MSGW + o4] = *(const float4*)&g_msg_i[(n0 + nd) * MSGW + o4];
    }
    __syncthreads();
    for (int i = t; i < 2304; i += 256) {
        int nd = i / 288, o4 = (i % 288) * 4;
        const float* br = sr + nd * MSGW;
        const float* bi = si + nd * MSGW;
        float vr[4], vi[4];
        #pragma unroll
        for (int c = 0; c < 4; c++) {
            int oidx = o4 + c;
            int k = oidx / 9;
            int mo = oidx - 9 * k;
            vr[c] = br[mo * 128 + k];
            vi[c] = bi[mo * 128 + k];
        }
        long ob = (long)(n0 + nd) * MSGW + o4;
        *(float4*)&out_r[ob] = make_float4(vr[0], vr[1], vr[2], vr[3]);
        *(float4*)&out_i[ob] = make_float4(vi[0], vi[1], vi[2], vi[3]);
    }
}

// ---------------- launch ---------------------------------------------------
extern "C" void kernel_launch(void* const* d_in, const int* in_sizes, int n_in,
                              void* d_out, int out_size) {
    const float* node_attrs = (const float*)d_in[0];
    const float* node_feats = (const float*)d_in[1];
    const float* yr        = (const float*)d_in[2];
    const float* yi        = (const float*)d_in[3];
    const float* ef        = (const float*)d_in[4];
    const int*   eidx      = (const int*)  d_in[5];
    const float* Wup       = (const float*)d_in[6];
    const float* Wskip     = (const float*)d_in[7];
    const float* W1        = (const float*)d_in[8];
    const float* W2        = (const float*)d_in[9];
    const float* W3        = (const float*)d_in[10];
    const float* W4        = (const float*)d_in[11];
    const float* Wl0       = (const float*)d_in[12];
    const float* Wl1       = (const float*)d_in[13];
    const float* Wl2       = (const float*)d_in[14];

    float* out   = (float*)d_out;
    float* out_r = out;
    float* out_i = out + OUTR_ELEMS;
    float* out_s = out + 2 * OUTR_ELEMS;

    cudaFuncSetAttribute(k_h,      cudaFuncAttributeMaxDynamicSharedMemorySize, H_SMEM);
    cudaFuncSetAttribute(k_sc,     cudaFuncAttributeMaxDynamicSharedMemorySize, SC_SMEM);
    cudaFuncSetAttribute(k_mlp123, cudaFuncAttributeMaxDynamicSharedMemorySize, MLP_SMEM);
    cudaFuncSetAttribute(k_gemm4,  cudaFuncAttributeMaxDynamicSharedMemorySize, G4_SMEM);
    cudaFuncSetAttribute(k_linear, cudaFuncAttributeMaxDynamicSharedMemorySize, LIN_SMEM);

    // idx 0..2
    k_reset<<<(NN + 255) / 256, 256>>>();
    k_count<<<(EE + 255) / 256, 256>>>(eidx);
    k_scan<<<1, 1024>>>();
    // idx 3: profiled launch (k_sc with float4 staging)
    k_sc<<<(NN + 31) / 32, 256, SC_SMEM>>>(node_feats, node_attrs, Wskip, out_s);
    // idx 4..7
    k_fill<<<(EE + 255) / 256, 256>>>(eidx);
    k_h<<<(NN + 31) / 32, 256, H_SMEM>>>(node_feats, Wup);
    k_mlp123<<<EE / 64, 256, MLP_SMEM>>>(ef, W1, W2, W3);
    k_gemm4<<<dim3(EE / 128, 3), 256, G4_SMEM>>>(W4);
    // idx 8
    k_gather<<<NN / 8, 256>>>(yr, yi);
    // idx 9..11: linear (in-place writeback into g_msg)
    k_linear<<<296, 256, LIN_SMEM>>>(Wl0, 1, 0);
    k_linear<<<296, 256, LIN_SMEM>>>(Wl1, 3, 128);
    k_linear<<<296, 256, LIN_SMEM>>>(Wl2, 5, 512);
    // idx 12: layout transpose to out
    k_transpose<<<NN / 8, 256>>>(out_r, out_i);
}